// round 17
// baseline (speedup 1.0000x reference)
#include <cuda_runtime.h>

#define Bn 8
#define Cn 24
#define Mn 960
#define Wn 15                   // 64-bit words per row (960/64)
#define ROWS (Bn*Mn)            // 7680
#define NWF (ROWS*Wn)           // frontier words
#define TR 8                    // rows per tile
#define TPI (Mn/TR)             // 120 tiles per image
#define NTILE (ROWS/TR)         // 960 tiles
#define HR 30                   // staged rows per tile (8 + 11 below + 11 above)

typedef unsigned long long u64;

// Only the frontier bitmap crosses CTAs through global memory.
__device__ u64 g_F[NWF];
// Handshake flags: 4 planes, each slot has exactly ONE consumer (reset by it).
__device__ int g_flag[4][NTILE];

__global__ void __launch_bounds__(128, 7) fused_kernel(const float* __restrict__ in,
                                                       float* __restrict__ out) {
    __shared__ u64 sF[HR][16];                 // frontier rows y0-11 .. y0+18
    __shared__ u64 sP[6][HR][16];              // hrode planes r=4,6,7,8,9,10
    __shared__ u64 sE[TR + 2][16];             // eroded rows (±1), word 15 = 0
    __shared__ u64 sB[TR][Wn];
    __shared__ float4 lut[16];

    const int t    = threadIdx.x;
    const int lane = t & 31;
    const int warp = t >> 5;
    const int tile = blockIdx.x;
    const int ii   = tile % TPI;
    const int row0 = tile * TR;                // global row = b*Mn + y
    const int b    = row0 / Mn;
    const int y0   = row0 - b * Mn;

    if (t < 16)
        lut[t] = make_float4(t & 1 ? 1.0f : 0.0f, t & 2 ? 1.0f : 0.0f,
                             t & 4 ? 1.0f : 0.0f, t & 8 ? 1.0f : 0.0f);

    // ── P0: ballot-pack own 8 rows (4 warps x 2 rows) -> sF rows 11..18 + g_F
#pragma unroll
    for (int i = 0; i < 2; i++) {
        int rr = warp * 2 + i;
        int y = y0 + rr;
        const float* p = in + ((size_t)(b * Cn + 1) * Mn + y) * Mn + lane;
        float v[30];
#pragma unroll
        for (int j = 0; j < 30; j++) v[j] = p[j * 32];
        unsigned bb[30];
#pragma unroll
        for (int j = 0; j < 30; j++) bb[j] = __ballot_sync(0xffffffffu, v[j] == 0.0f);
        if (lane < Wn) {
            unsigned lo = 0, hi = 0;
#pragma unroll
            for (int k = 0; k < Wn; k++)
                if (lane == k) { lo = bb[2 * k]; hi = bb[2 * k + 1]; }
            u64 word = ((u64)hi << 32) | lo;
            sF[11 + rr][lane] = word;
            g_F[(size_t)(row0 + rr) * Wn + lane] = word;
        }
    }
    __syncthreads();

    // ── P1: publish + spin on 4 vertical neighbor tiles (all 960 co-resident)
    if (t == 0) {
        __threadfence();
        atomicExch(&g_flag[0][tile], 1);
        atomicExch(&g_flag[1][tile], 1);
        atomicExch(&g_flag[2][tile], 1);
        atomicExch(&g_flag[3][tile], 1);
        if (ii >= 1)       while (atomicAdd(&g_flag[0][tile - 1], 0) == 0) {}
        if (ii >= 2)       while (atomicAdd(&g_flag[1][tile - 2], 0) == 0) {}
        if (ii <= TPI - 2) while (atomicAdd(&g_flag[2][tile + 1], 0) == 0) {}
        if (ii <= TPI - 3) while (atomicAdd(&g_flag[3][tile + 2], 0) == 0) {}
        __threadfence();
    }
    __syncthreads();

    // ── P2: load 22 halo F rows from global (rows 0..10 and 19..29)
    for (int task = t; task < 22 * Wn; task += 128) {
        int k = task / Wn, w = task - k * Wn;
        int hr = (k < 11) ? k : k + TR;               // smem row 0..10 / 19..29
        int y = y0 + hr - 11;
        u64 word = 0ULL;
        if (y >= 0 && y < Mn)
            word = g_F[(size_t)(b * Mn + y) * Wn + w];
        sF[hr][w] = word;
    }
    __syncthreads();

    // ── P3: hrode for all 30 staged rows, planes stay in smem (450 tasks)
    for (int task = t; task < HR * Wn; task += 128) {
        int rr = task / Wn, w = task - rr * Wn;
        u64 c = sF[rr][w];
        u64 l = (w > 0)      ? sF[rr][w - 1] : 0ULL;
        u64 r = (w < Wn - 1) ? sF[rr][w + 1] : 0ULL;
        u64 acc = c;
#pragma unroll
        for (int d = 1; d <= 10; d++) {
            acc &= ((c << d) | (l >> (64 - d))) & ((c >> d) | (r << (64 - d)));
            if (d == 4)       sP[0][rr][w] = acc;
            else if (d == 6)  sP[1][rr][w] = acc;
            else if (d == 7)  sP[2][rr][w] = acc;
            else if (d == 8)  sP[3][rr][w] = acc;
            else if (d == 9)  sP[4][rr][w] = acc;
            else if (d == 10) sP[5][rr][w] = acc;
        }
    }
    __syncthreads();

    // ── release consumed flag slots (exactly one consumer each)
    if (t == 0) {
        if (ii >= 1)       atomicExch(&g_flag[0][tile - 1], 0);
        if (ii >= 2)       atomicExch(&g_flag[1][tile - 2], 0);
        if (ii <= TPI - 2) atomicExch(&g_flag[2][tile + 1], 0);
        if (ii <= TPI - 3) atomicExch(&g_flag[3][tile + 2], 0);
    }

    // ── P4: vertical 21-term AND, all smem (150 tasks) + zero sE pads
    if (t < TR + 2) sE[t][15] = 0ULL;
    for (int task = t; task < (TR + 2) * Wn; task += 128) {
        int re = task / Wn, w = task - re * Wn;
        int y = y0 + re - 1;
        u64 e = 0ULL;
        if (y >= 10 && y <= Mn - 11) {
            int h = 10 + re;                          // smem row of dy=0
            u64 a0 = (sP[5][h][w]     & sP[4][h - 1][w]) & (sP[4][h + 1][w] & sP[4][h - 2][w]);
            u64 a1 = (sP[4][h + 2][w] & sP[4][h - 3][w]) & (sP[4][h + 3][w] & sP[4][h - 4][w]);
            u64 a2 = (sP[4][h + 4][w] & sP[3][h - 5][w]) & (sP[3][h + 5][w] & sP[3][h - 6][w]);
            u64 a3 = (sP[3][h + 6][w] & sP[2][h - 7][w]) & (sP[2][h + 7][w] & sP[1][h - 8][w]);
            u64 a4 = (sP[1][h + 8][w] & sP[0][h - 9][w]) & (sP[0][h + 9][w] & sF[h - 10][w]);
            e = ((a0 & a1) & (a2 & a3)) & (a4 & sF[h + 10][w]);
        }
        sE[re][w] = e;
    }
    __syncthreads();

    // ── P5: border = dilate(e, cross) & ~e (120 tasks)
    if (t < TR * Wn) {
        int rr = t / Wn, w = t - rr * Wn;
        u64 e  = sE[rr + 1][w];
        u64 eu = sE[rr][w];
        u64 ed = sE[rr + 2][w];
        u64 l  = (w > 0) ? sE[rr + 1][w - 1] : 0ULL;
        u64 r  = sE[rr + 1][w + 1];                   // pad word 0 at w=14
        u64 d = e | eu | ed | (e << 1) | (l >> 63) | (e >> 1) | (r << 63);
        sB[rr][w] = d & ~e;
    }
    __syncthreads();

    // ── P6: expand 8 rows x 240 float4 = 1920 chunks, 15/thread, coalesced
    float4* o = (float4*)out + (size_t)row0 * 240;
#pragma unroll
    for (int k = 0; k < 15; k++) {
        int c = k * 128 + t;                          // 0..1919 == rr*240+cc
        int rr = c / 240, cc = c - rr * 240;
        unsigned nib = (unsigned)(sB[rr][cc >> 4] >> ((cc & 15) << 2)) & 15u;
        o[c] = lut[nib];
    }
}

extern "C" void kernel_launch(void* const* d_in, const int* in_sizes, int n_in,
                              void* d_out, int out_size) {
    const float* map_features = (const float*)d_in[0];
    float* out = (float*)d_out;
    fused_kernel<<<NTILE, 128>>>(map_features, out);  // 960 blocks, single launch
}